// round 9
// baseline (speedup 1.0000x reference)
#include <cuda_runtime.h>
#include <cuda_fp16.h>
#include <cstdint>

#define NUM_EDGE  14
#define NUM_NODES 10000
#define BATCH     8192
#define EDGE_IN   1536
#define HET_IN    1792
#define DOUT      128

__device__ __half g_agg[(size_t)BATCH * HET_IN];
__device__ __half g_WE [(size_t)NUM_EDGE * EDGE_IN * DOUT];
__device__ __half g_WH [(size_t)HET_IN * DOUT];
__device__ float  g_part[2][(size_t)BATCH * DOUT];

__device__ __forceinline__ uint32_t f2h2(float x, float y) {
    __half2 h = __floats2half2_rn(x, y);
    return *(uint32_t*)&h;
}

__device__ __forceinline__ void cp16(uint32_t s, const void* g) {
    asm volatile("cp.async.cg.shared.global [%0], [%1], 16;\n" :: "r"(s), "l"(g));
}
__device__ __forceinline__ void cp_commit() { asm volatile("cp.async.commit_group;\n"); }
template <int N> __device__ __forceinline__ void cp_wait() {
    asm volatile("cp.async.wait_group %0;\n" :: "n"(N));
}

__device__ __forceinline__ void ldsm_x4(uint32_t* r, uint32_t a) {
    asm volatile("ldmatrix.sync.aligned.m8n8.x4.shared.b16 {%0,%1,%2,%3}, [%4];"
        : "=r"(r[0]), "=r"(r[1]), "=r"(r[2]), "=r"(r[3]) : "r"(a));
}
__device__ __forceinline__ void ldsm_x4_t(uint32_t* r, uint32_t a) {
    asm volatile("ldmatrix.sync.aligned.m8n8.x4.trans.shared.b16 {%0,%1,%2,%3}, [%4];"
        : "=r"(r[0]), "=r"(r[1]), "=r"(r[2]), "=r"(r[3]) : "r"(a));
}
__device__ __forceinline__ void sts128(uint32_t a, uint32_t x, uint32_t y, uint32_t z, uint32_t w) {
    asm volatile("st.shared.v4.b32 [%0], {%1,%2,%3,%4};" :: "r"(a), "r"(x), "r"(y), "r"(z), "r"(w));
}

__device__ __forceinline__ void mma_f16(float* c, const uint32_t* a, const uint32_t* b) {
    asm volatile(
        "mma.sync.aligned.m16n8k16.row.col.f32.f16.f16.f32 "
        "{%0,%1,%2,%3}, {%4,%5,%6,%7}, {%8,%9}, {%0,%1,%2,%3};\n"
        : "+f"(c[0]), "+f"(c[1]), "+f"(c[2]), "+f"(c[3])
        : "r"(a[0]), "r"(a[1]), "r"(a[2]), "r"(a[3]), "r"(b[0]), "r"(b[1]));
}

__global__ void cvt_to_half(const float4* __restrict__ s, __half2* __restrict__ d, int n4) {
    int i = blockIdx.x * blockDim.x + threadIdx.x;
    if (i < n4) {
        float4 v = s[i];
        d[2 * i]     = __floats2half2_rn(v.x, v.y);
        d[2 * i + 1] = __floats2half2_rn(v.z, v.w);
    }
}

// ============================================================================
// GEMM1 (EDGE): 256 threads, BM=128, 8 warps (2x4 of 64x32 warp tiles),
// 4-slot ring, wait<1>, ONE K-tile per barrier, and register fragment
// double-buffering: fragments for kk-step n+1 (cross-tile too) are LDSM'd
// while step n's MMAs issue from already-resident registers.
// ============================================================================
__global__ void __launch_bounds__(256, 2) hetagg_edge(
    const float* __restrict__ Afeat,
    const int*   __restrict__ gid,
    const float* __restrict__ ball)
{
    constexpr int KT    = EDGE_IN / 32;     // 48
    constexpr int A_ST  = 128 * 80;         // 10240
    constexpr int B_ST  = 32 * 256;         // 8192
    constexpr int OFF_B = 4 * A_ST;

    extern __shared__ char smem[];
    const uint32_t sb = (uint32_t)__cvta_generic_to_shared(smem);

    const int e    = blockIdx.y;
    const int tid  = threadIdx.x;
    const int l    = tid & 31;
    const int warp = tid >> 5;
    const int wm   = warp >> 2;     // 0..1 (64-row band)
    const int wn   = warp & 3;      // 0..3 (32-col band)
    const int m0   = blockIdx.x * 128;

    // ---- B loader: 2 cp16/thread/ktile (8KB tile, 256 threads)
    const int bk = tid >> 3;
    const int bc = (tid & 7) * 2;
    const __half* bsrc = g_WE + (size_t)e * EDGE_IN * DOUT + (size_t)bk * DOUT + bc * 8;
    const uint32_t bdst0 = sb + OFF_B + bk * 256 + ((bc >> 3) * 128) + (((bc & 7) ^ (bk & 7)) * 16);
    const int bc1 = bc + 1;
    const uint32_t bdst1 = sb + OFF_B + bk * 256 + ((bc1 >> 3) * 128) + (((bc1 & 7) ^ (bk & 7)) * 16);
    auto cpB = [&](int s, int kt) {
        const __half* src = bsrc + (size_t)kt * 32 * DOUT;
        cp16(bdst0 + s * B_ST, src);
        cp16(bdst1 + s * B_ST, src + 8);
    };

    // ---- A loader: 2 threads/row, 16 floats -> 8 half2 regs (convert at LDG)
    const int arow = tid >> 1, ah = tid & 1;
    const float* agF = Afeat + (size_t)e * NUM_NODES * EDGE_IN
                             + (size_t)gid[m0 + arow] * EDGE_IN + ah * 16;
    const uint32_t aSt = sb + arow * 80 + ah * 32;

    uint32_t av[8];   // single prefetch buffer (half2-packed), 1-iteration slack
    auto ldA = [&](int kt) {
        const float4* p = (const float4*)(agF + kt * 32);
        float4 v0 = p[0], v1 = p[1], v2 = p[2], v3 = p[3];
        av[0] = f2h2(v0.x, v0.y); av[1] = f2h2(v0.z, v0.w);
        av[2] = f2h2(v1.x, v1.y); av[3] = f2h2(v1.z, v1.w);
        av[4] = f2h2(v2.x, v2.y); av[5] = f2h2(v2.z, v2.w);
        av[6] = f2h2(v3.x, v3.y); av[7] = f2h2(v3.z, v3.w);
    };
    auto stsA = [&](int s) {
        sts128(aSt + s * A_ST,      av[0], av[1], av[2], av[3]);
        sts128(aSt + s * A_ST + 16, av[4], av[5], av[6], av[7]);
    };

    // ---- fragment loaders
    auto fragA = [&](uint32_t* af, int s, int kk) {   // af[16]
        const uint32_t base = sb + s * A_ST + kk * 32 + (l >> 4) * 16;
        #pragma unroll
        for (int mt = 0; mt < 4; ++mt)
            ldsm_x4(af + 4 * mt, base + (wm * 64 + mt * 16 + (l & 15)) * 80);
    };
    auto fragB = [&](uint32_t* bf, int s, int kk) {   // bf[8] = bf[4nt][2]
        const uint32_t base = sb + OFF_B + s * B_ST;
        #pragma unroll
        for (int ntp = 0; ntp < 2; ++ntp) {
            const int krow = kk * 16 + ((l >> 3) & 1) * 8 + (l & 7);
            const int c    = wn * 4 + ntp * 2 + (l >> 4);
            uint32_t r[4];
            ldsm_x4_t(r, base + krow * 256 + ((c >> 3) * 128)
                         + (((c & 7) ^ (krow & 7)) << 4));
            bf[(2 * ntp) * 2 + 0] = r[0]; bf[(2 * ntp) * 2 + 1] = r[1];
            bf[(2 * ntp + 1) * 2 + 0] = r[2]; bf[(2 * ntp + 1) * 2 + 1] = r[3];
        }
    };

    float acc[4][4][4];
    #pragma unroll
    for (int i = 0; i < 4; ++i)
        #pragma unroll
        for (int j = 0; j < 4; ++j)
            #pragma unroll
            for (int q = 0; q < 4; ++q) acc[i][j][q] = 0.f;

    auto mma_all = [&](const uint32_t* af, const uint32_t* bf) {
        #pragma unroll
        for (int mt = 0; mt < 4; ++mt)
            #pragma unroll
            for (int nt = 0; nt < 4; ++nt)
                mma_f16(acc[mt][nt], af + 4 * mt, bf + 2 * nt);
    };

    // ---- prologue: A tiles 0,1 via STS; B tiles 0,1,2 via cp.async; av <- tile 2
    ldA(0); stsA(0);
    ldA(1); stsA(1);
    cpB(0, 0); cp_commit();
    cpB(1, 1); cp_commit();
    cpB(2, 2); cp_commit();
    ldA(2);

    cp_wait<1>();        // B tiles 0,1 landed
    __syncthreads();     // A tiles 0,1 visible

    uint32_t afA[2][16], bfB[2][8];
    fragA(afA[0], 0, 0); fragB(bfB[0], 0, 0);

    for (int kt = 0; kt < KT; ++kt) {
        if (kt > 0) { cp_wait<1>(); __syncthreads(); }   // tiles <= kt+1 landed; slot (kt+2)&3 free

        // producers: A tile kt+2 (from av), B tile kt+3, av <- tile kt+3
        if (kt + 2 < KT) stsA((kt + 2) & 3);
        if (kt + 3 < KT) { cpB((kt + 3) & 3, kt + 3); }
        cp_commit();
        if (kt + 3 < KT) ldA(kt + 3);

        // step kk0: prefetch (kt,kk1) into buf1, then MMA buf0 (resident)
        fragA(afA[1], kt & 3, 1); fragB(bfB[1], kt & 3, 1);
        mma_all(afA[0], bfB[0]);

        // step kk1: prefetch (kt+1,kk0) into buf0, then MMA buf1 (resident)
        fragA(afA[0], (kt + 1) & 3, 0); fragB(bfB[0], (kt + 1) & 3, 0);
        mma_all(afA[1], bfB[1]);
    }

    const float* bias = ball + e * DOUT;
    #pragma unroll
    for (int mt = 0; mt < 4; ++mt) {
        const int row = m0 + wm * 64 + mt * 16 + (l >> 2);
        #pragma unroll
        for (int nt = 0; nt < 4; ++nt) {
            const int col = wn * 32 + nt * 8 + (l & 3) * 2;
            const float2 bv = *(const float2*)&bias[col];
            float x0 = acc[mt][nt][0] + bv.x; x0 = x0 > 0.f ? x0 : 0.01f * x0;
            float x1 = acc[mt][nt][1] + bv.y; x1 = x1 > 0.f ? x1 : 0.01f * x1;
            float x2 = acc[mt][nt][2] + bv.x; x2 = x2 > 0.f ? x2 : 0.01f * x2;
            float x3 = acc[mt][nt][3] + bv.y; x3 = x3 > 0.f ? x3 : 0.01f * x3;
            *(__half2*)&g_agg[(size_t)row * HET_IN + e * DOUT + col]       = __floats2half2_rn(x0, x1);
            *(__half2*)&g_agg[(size_t)(row + 8) * HET_IN + e * DOUT + col] = __floats2half2_rn(x2, x3);
        }
    }
}

// ============================================================================
// GEMM2 (HET): split-K=2 (proven R8). BM=64, 8 warps (2x4 of 32x32),
// 3-slot ring, one K-tile per barrier. Partials -> g_part[split].
// ============================================================================
__global__ void __launch_bounds__(256, 3) hetagg_het(void)
{
    constexpr int KT_H  = (HET_IN / 2) / 32;   // 28
    constexpr int A_ST  = 64 * 80;
    constexpr int B_ST  = 32 * 256;
    constexpr int OFF_B = 3 * A_ST;

    extern __shared__ char smem[];
    const uint32_t sb = (uint32_t)__cvta_generic_to_shared(smem);

    const int tid  = threadIdx.x;
    const int l    = tid & 31;
    const int warp = tid >> 5;
    const int wm   = warp >> 2;
    const int wn   = warp & 3;
    const int m0   = blockIdx.x * 64;
    const int kOff = blockIdx.y * (HET_IN / 2);

    const int bk = tid >> 3;
    const int bc = (tid & 7) * 2;
    const __half* bsrc = g_WH + (size_t)(kOff + bk) * DOUT + bc * 8;
    const uint32_t bdst0 = sb + OFF_B + bk * 256 + ((bc >> 3) * 128) + (((bc & 7) ^ (bk & 7)) * 16);
    const int bc1 = bc + 1;
    const uint32_t bdst1 = sb + OFF_B + bk * 256 + ((bc1 >> 3) * 128) + (((bc1 & 7) ^ (bk & 7)) * 16);

    const int arow = tid >> 2, ac = tid & 3;
    const __half* agH  = g_agg + (size_t)(m0 + arow) * HET_IN + kOff + ac * 8;
    const uint32_t adst = sb + arow * 80 + ac * 16;

    auto fill = [&](int s, int kt) {
        cp16(adst + s * A_ST, agH + kt * 32);
        const __half* src = bsrc + (size_t)kt * 32 * DOUT;
        cp16(bdst0 + s * B_ST, src);
        cp16(bdst1 + s * B_ST, src + 8);
        cp_commit();
    };

    float acc[2][4][4];
    #pragma unroll
    for (int i = 0; i < 2; ++i)
        #pragma unroll
        for (int j = 0; j < 4; ++j)
            #pragma unroll
            for (int q = 0; q < 4; ++q) acc[i][j][q] = 0.f;

    fill(0, 0); fill(1, 1);

    for (int kt = 0; kt < KT_H; ++kt) {
        cp_wait<1>();
        __syncthreads();

        if (kt + 2 < KT_H) fill((kt + 2) % 3, kt + 2);
        else               cp_commit();

        const int s = kt % 3;
        const uint32_t Ab = sb + s * A_ST;
        const uint32_t Bb = sb + OFF_B + s * B_ST;
        #pragma unroll
        for (int kk = 0; kk < 2; ++kk) {
            uint32_t af[2][4];
            #pragma unroll
            for (int mt = 0; mt < 2; ++mt)
                ldsm_x4(af[mt], Ab + (wm * 32 + mt * 16 + (l & 15)) * 80
                                   + kk * 32 + (l >> 4) * 16);
            uint32_t bf[4][2];
            #pragma unroll
            for (int ntp = 0; ntp < 2; ++ntp) {
                const int krow = kk * 16 + ((l >> 3) & 1) * 8 + (l & 7);
                const int c    = wn * 4 + ntp * 2 + (l >> 4);
                uint32_t r[4];
                ldsm_x4_t(r, Bb + krow * 256 + ((c >> 3) * 128)
                             + (((c & 7) ^ (krow & 7)) << 4));
                bf[2 * ntp][0] = r[0];     bf[2 * ntp][1] = r[1];
                bf[2 * ntp + 1][0] = r[2]; bf[2 * ntp + 1][1] = r[3];
            }
            #pragma unroll
            for (int mt = 0; mt < 2; ++mt)
                #pragma unroll
                for (int nt = 0; nt < 4; ++nt)
                    mma_f16(acc[mt][nt], af[mt], bf[nt]);
        }
    }

    float* part = g_part[blockIdx.y];
    #pragma unroll
    for (int mt = 0; mt < 2; ++mt) {
        const int row = m0 + wm * 32 + mt * 16 + (l >> 2);
        #pragma unroll
        for (int nt = 0; nt < 4; ++nt) {
            const int col = wn * 32 + nt * 8 + (l & 3) * 2;
            *(float2*)&part[(size_t)row * DOUT + col] =
                make_float2(acc[mt][nt][0], acc[mt][nt][1]);
            *(float2*)&part[(size_t)(row + 8) * DOUT + col] =
                make_float2(acc[mt][nt][2], acc[mt][nt][3]);
        }
    }
}

__global__ void het_reduce(const float* __restrict__ ball, float* __restrict__ out) {
    const int i = blockIdx.x * blockDim.x + threadIdx.x;
    const int n4 = BATCH * DOUT / 4;
    if (i >= n4) return;
    float4 a = ((const float4*)g_part[0])[i];
    float4 b = ((const float4*)g_part[1])[i];
    const int col = (i * 4) & (DOUT - 1);
    float4 bv = *(const float4*)&ball[col];
    float x0 = a.x + b.x + bv.x; x0 = x0 > 0.f ? x0 : 0.01f * x0;
    float x1 = a.y + b.y + bv.y; x1 = x1 > 0.f ? x1 : 0.01f * x1;
    float x2 = a.z + b.z + bv.z; x2 = x2 > 0.f ? x2 : 0.01f * x2;
    float x3 = a.w + b.w + bv.w; x3 = x3 > 0.f ? x3 : 0.01f * x3;
    ((float4*)out)[i] = make_float4(x0, x1, x2, x3);
}

extern "C" void kernel_launch(void* const* d_in, const int* in_sizes, int n_in,
                              void* d_out, int out_size) {
    const float* features = (const float*)d_in[0];
    const float* W_edge   = (const float*)d_in[1];
    const float* b_edge   = (const float*)d_in[2];
    const float* W_het    = (const float*)d_in[3];
    const float* b_het    = (const float*)d_in[4];
    const int*   gid      = (const int*)d_in[5];
    float* out = (float*)d_out;

    __half* we; cudaGetSymbolAddress((void**)&we, g_WE);
    __half* wh; cudaGetSymbolAddress((void**)&wh, g_WH);

    const int n4e = NUM_EDGE * EDGE_IN * DOUT / 4;
    const int n4h = HET_IN * DOUT / 4;
    cvt_to_half<<<(n4e + 255) / 256, 256>>>((const float4*)W_edge, (__half2*)we, n4e);
    cvt_to_half<<<(n4h + 255) / 256, 256>>>((const float4*)W_het, (__half2*)wh, n4h);

    const int smem1 = 4 * (128 * 80) + 4 * (32 * 256);  // 73728
    const int smem2 = 3 * (64 * 80)  + 3 * (32 * 256);  // 39936

    cudaFuncSetAttribute(hetagg_edge,
                         cudaFuncAttributeMaxDynamicSharedMemorySize, smem1);
    cudaFuncSetAttribute(hetagg_het,
                         cudaFuncAttributeMaxDynamicSharedMemorySize, smem2);

    dim3 g1(BATCH / 128, NUM_EDGE);
    hetagg_edge<<<g1, 256, smem1>>>(features, gid, b_edge);

    dim3 g2(BATCH / 64, 2);
    hetagg_het<<<g2, 256, smem2>>>();

    const int n4o = BATCH * DOUT / 4;
    het_reduce<<<(n4o + 255) / 256, 256>>>(b_het, out);
}

// round 10
// speedup vs baseline: 1.1358x; 1.1358x over previous
#include <cuda_runtime.h>
#include <cuda_fp16.h>
#include <cstdint>

#define NUM_EDGE  14
#define NUM_NODES 10000
#define BATCH     8192
#define EDGE_IN   1536
#define HET_IN    1792
#define DOUT      128

__device__ __half g_agg[(size_t)BATCH * HET_IN];
__device__ __half g_WE [(size_t)NUM_EDGE * EDGE_IN * DOUT];
__device__ __half g_WH [(size_t)HET_IN * DOUT];
__device__ float  g_part[2][(size_t)BATCH * DOUT];

__device__ __forceinline__ uint32_t f2h2(float x, float y) {
    __half2 h = __floats2half2_rn(x, y);
    return *(uint32_t*)&h;
}

__device__ __forceinline__ void cp16(uint32_t s, const void* g) {
    asm volatile("cp.async.cg.shared.global [%0], [%1], 16;\n" :: "r"(s), "l"(g));
}
__device__ __forceinline__ void cp_commit() { asm volatile("cp.async.commit_group;\n"); }
template <int N> __device__ __forceinline__ void cp_wait() {
    asm volatile("cp.async.wait_group %0;\n" :: "n"(N));
}

__device__ __forceinline__ void ldsm_x4(uint32_t* r, uint32_t a) {
    asm volatile("ldmatrix.sync.aligned.m8n8.x4.shared.b16 {%0,%1,%2,%3}, [%4];"
        : "=r"(r[0]), "=r"(r[1]), "=r"(r[2]), "=r"(r[3]) : "r"(a));
}
__device__ __forceinline__ void ldsm_x4_t(uint32_t* r, uint32_t a) {
    asm volatile("ldmatrix.sync.aligned.m8n8.x4.trans.shared.b16 {%0,%1,%2,%3}, [%4];"
        : "=r"(r[0]), "=r"(r[1]), "=r"(r[2]), "=r"(r[3]) : "r"(a));
}
__device__ __forceinline__ void sts128(uint32_t a, uint32_t x, uint32_t y, uint32_t z, uint32_t w) {
    asm volatile("st.shared.v4.b32 [%0], {%1,%2,%3,%4};" :: "r"(a), "r"(x), "r"(y), "r"(z), "r"(w));
}

__device__ __forceinline__ void mma_f16(float* c, const uint32_t* a, const uint32_t* b) {
    asm volatile(
        "mma.sync.aligned.m16n8k16.row.col.f32.f16.f16.f32 "
        "{%0,%1,%2,%3}, {%4,%5,%6,%7}, {%8,%9}, {%0,%1,%2,%3};\n"
        : "+f"(c[0]), "+f"(c[1]), "+f"(c[2]), "+f"(c[3])
        : "r"(a[0]), "r"(a[1]), "r"(a[2]), "r"(a[3]), "r"(b[0]), "r"(b[1]));
}

__global__ void cvt_to_half(const float4* __restrict__ s, __half2* __restrict__ d, int n4) {
    int i = blockIdx.x * blockDim.x + threadIdx.x;
    if (i < n4) {
        float4 v = s[i];
        d[2 * i]     = __floats2half2_rn(v.x, v.y);
        d[2 * i + 1] = __floats2half2_rn(v.z, v.w);
    }
}

// ============================================================================
// GEMM1 (EDGE): proven R4 skeleton (BM=128, 256 thr, warp 64x32, 3-slot ring,
// wait<1>, one K-tile per barrier) + register-lean fragment pipelining:
// A fragments ping-pong between two 4-reg buffers at mt granularity, B
// fragments double-buffered across kk. MMAs issue from resident registers
// while the next ldsm.x4 is in flight -> LDSM latency and crossbar time
// overlap the tensor pipe instead of serializing with it.
// ============================================================================
__global__ void __launch_bounds__(256, 2) hetagg_edge(
    const float* __restrict__ Afeat,
    const int*   __restrict__ gid,
    const float* __restrict__ ball)
{
    constexpr int KT    = EDGE_IN / 32;     // 48
    constexpr int A_ST  = 128 * 80;         // 10240
    constexpr int B_ST  = 32 * 256;         // 8192
    constexpr int OFF_B = 3 * A_ST;

    extern __shared__ char smem[];
    const uint32_t sb = (uint32_t)__cvta_generic_to_shared(smem);

    const int e    = blockIdx.y;
    const int tid  = threadIdx.x;
    const int l    = tid & 31;
    const int warp = tid >> 5;
    const int wm   = warp >> 2;     // 0..1 (64-row band)
    const int wn   = warp & 3;      // 0..3 (32-col band)
    const int m0   = blockIdx.x * 128;

    // ---- B loader: 2 cp16/thread/ktile
    const int bk = tid >> 3;
    const int bc = (tid & 7) * 2;
    const __half* bsrc = g_WE + (size_t)e * EDGE_IN * DOUT + (size_t)bk * DOUT + bc * 8;
    const uint32_t bdst0 = sb + OFF_B + bk * 256 + ((bc >> 3) * 128) + (((bc & 7) ^ (bk & 7)) * 16);
    const int bc1 = bc + 1;
    const uint32_t bdst1 = sb + OFF_B + bk * 256 + ((bc1 >> 3) * 128) + (((bc1 & 7) ^ (bk & 7)) * 16);
    auto cpB = [&](int s, int kt) {
        const __half* src = bsrc + (size_t)kt * 32 * DOUT;
        cp16(bdst0 + s * B_ST, src);
        cp16(bdst1 + s * B_ST, src + 8);
    };

    // ---- A loader: 2 threads/row, 16 floats -> 8 half2 regs (convert at LDG)
    const int arow = tid >> 1, ah = tid & 1;
    const float* agF = Afeat + (size_t)e * NUM_NODES * EDGE_IN
                             + (size_t)gid[m0 + arow] * EDGE_IN + ah * 16;
    const uint32_t aSt = sb + arow * 80 + ah * 32;

    uint32_t av[8];
    auto ldA = [&](int kt) {
        const float4* p = (const float4*)(agF + kt * 32);
        float4 v0 = p[0], v1 = p[1], v2 = p[2], v3 = p[3];
        av[0] = f2h2(v0.x, v0.y); av[1] = f2h2(v0.z, v0.w);
        av[2] = f2h2(v1.x, v1.y); av[3] = f2h2(v1.z, v1.w);
        av[4] = f2h2(v2.x, v2.y); av[5] = f2h2(v2.z, v2.w);
        av[6] = f2h2(v3.x, v3.y); av[7] = f2h2(v3.z, v3.w);
    };
    auto stsA = [&](int s) {
        sts128(aSt + s * A_ST,      av[0], av[1], av[2], av[3]);
        sts128(aSt + s * A_ST + 16, av[4], av[5], av[6], av[7]);
    };

    // ---- fragment loaders
    auto fragA1 = [&](uint32_t* af, int s, int kk, int mt) {   // one ldsm.x4, 4 regs
        ldsm_x4(af, sb + s * A_ST + (wm * 64 + mt * 16 + (l & 15)) * 80
                   + kk * 32 + (l >> 4) * 16);
    };
    auto fragB = [&](uint32_t* bf, int s, int kk) {            // bf[8]
        const uint32_t base = sb + OFF_B + s * B_ST;
        #pragma unroll
        for (int ntp = 0; ntp < 2; ++ntp) {
            const int krow = kk * 16 + ((l >> 3) & 1) * 8 + (l & 7);
            const int c    = wn * 4 + ntp * 2 + (l >> 4);
            uint32_t r[4];
            ldsm_x4_t(r, base + krow * 256 + ((c >> 3) * 128)
                         + (((c & 7) ^ (krow & 7)) << 4));
            bf[(2 * ntp) * 2 + 0] = r[0]; bf[(2 * ntp) * 2 + 1] = r[1];
            bf[(2 * ntp + 1) * 2 + 0] = r[2]; bf[(2 * ntp + 1) * 2 + 1] = r[3];
        }
    };

    float acc[4][4][4];
    #pragma unroll
    for (int i = 0; i < 4; ++i)
        #pragma unroll
        for (int j = 0; j < 4; ++j)
            #pragma unroll
            for (int q = 0; q < 4; ++q) acc[i][j][q] = 0.f;

    auto mma4 = [&](float (*a)[4], const uint32_t* af, const uint32_t* bf) {
        #pragma unroll
        for (int nt = 0; nt < 4; ++nt)
            mma_f16(a[nt], af, bf + 2 * nt);
    };

    // ---- prologue (R4): A tiles 0(,1 in regs) STS'd/held; B tiles 0,1 via cp.async
    ldA(0); stsA(0); cpB(0, 0); cp_commit();
    ldA(1);          cpB(1, 1); cp_commit();

    int slot = 0, slotP = 1, slotF = 2;
    for (int kt = 0; kt < KT; ++kt) {
        cp_wait<1>();        // B of tile kt landed
        __syncthreads();     // A of tile kt visible; slotF consumed 2 iters ago -> free

        if (kt + 1 < KT) stsA(slotP);
        if (kt + 2 < KT) { cpB(slotF, kt + 2); }
        cp_commit();
        if (kt + 2 < KT) ldA(kt + 2);

        // ---- pipelined compute of tile kt from 'slot'
        {
            uint32_t bf0[8], bf1[8], afA[4], afB[4];
            fragB(bf0, slot, 0);
            fragA1(afA, slot, 0, 0);
            // kk = 0
            fragA1(afB, slot, 0, 1);  mma4(acc[0], afA, bf0);
            fragA1(afA, slot, 0, 2);  mma4(acc[1], afB, bf0);
            fragA1(afB, slot, 0, 3);  mma4(acc[2], afA, bf0);
            fragB(bf1, slot, 1);      mma4(acc[3], afB, bf0);
            // kk = 1
            fragA1(afA, slot, 1, 0);
            fragA1(afB, slot, 1, 1);  mma4(acc[0], afA, bf1);
            fragA1(afA, slot, 1, 2);  mma4(acc[1], afB, bf1);
            fragA1(afB, slot, 1, 3);  mma4(acc[2], afA, bf1);
                                      mma4(acc[3], afB, bf1);
        }

        const int t = slot; slot = slotP; slotP = slotF; slotF = t;
    }

    const float* bias = ball + e * DOUT;
    #pragma unroll
    for (int mt = 0; mt < 4; ++mt) {
        const int row = m0 + wm * 64 + mt * 16 + (l >> 2);
        #pragma unroll
        for (int nt = 0; nt < 4; ++nt) {
            const int col = wn * 32 + nt * 8 + (l & 3) * 2;
            const float2 bv = *(const float2*)&bias[col];
            float x0 = acc[mt][nt][0] + bv.x; x0 = x0 > 0.f ? x0 : 0.01f * x0;
            float x1 = acc[mt][nt][1] + bv.y; x1 = x1 > 0.f ? x1 : 0.01f * x1;
            float x2 = acc[mt][nt][2] + bv.x; x2 = x2 > 0.f ? x2 : 0.01f * x2;
            float x3 = acc[mt][nt][3] + bv.y; x3 = x3 > 0.f ? x3 : 0.01f * x3;
            *(__half2*)&g_agg[(size_t)row * HET_IN + e * DOUT + col]       = __floats2half2_rn(x0, x1);
            *(__half2*)&g_agg[(size_t)(row + 8) * HET_IN + e * DOUT + col] = __floats2half2_rn(x2, x3);
        }
    }
}

// ============================================================================
// GEMM2 (HET): split-K=2 (proven R8, 18.7us). BM=64, 8 warps (2x4 of 32x32),
// 3-slot ring, one K-tile per barrier. Partials -> g_part[split].
// ============================================================================
__global__ void __launch_bounds__(256, 3) hetagg_het(void)
{
    constexpr int KT_H  = (HET_IN / 2) / 32;   // 28
    constexpr int A_ST  = 64 * 80;
    constexpr int B_ST  = 32 * 256;
    constexpr int OFF_B = 3 * A_ST;

    extern __shared__ char smem[];
    const uint32_t sb = (uint32_t)__cvta_generic_to_shared(smem);

    const int tid  = threadIdx.x;
    const int l    = tid & 31;
    const int warp = tid >> 5;
    const int wm   = warp >> 2;
    const int wn   = warp & 3;
    const int m0   = blockIdx.x * 64;
    const int kOff = blockIdx.y * (HET_IN / 2);

    const int bk = tid >> 3;
    const int bc = (tid & 7) * 2;
    const __half* bsrc = g_WH + (size_t)(kOff + bk) * DOUT + bc * 8;
    const uint32_t bdst0 = sb + OFF_B + bk * 256 + ((bc >> 3) * 128) + (((bc & 7) ^ (bk & 7)) * 16);
    const int bc1 = bc + 1;
    const uint32_t bdst1 = sb + OFF_B + bk * 256 + ((bc1 >> 3) * 128) + (((bc1 & 7) ^ (bk & 7)) * 16);

    const int arow = tid >> 2, ac = tid & 3;
    const __half* agH  = g_agg + (size_t)(m0 + arow) * HET_IN + kOff + ac * 8;
    const uint32_t adst = sb + arow * 80 + ac * 16;

    auto fill = [&](int s, int kt) {
        cp16(adst + s * A_ST, agH + kt * 32);
        const __half* src = bsrc + (size_t)kt * 32 * DOUT;
        cp16(bdst0 + s * B_ST, src);
        cp16(bdst1 + s * B_ST, src + 8);
        cp_commit();
    };

    float acc[2][4][4];
    #pragma unroll
    for (int i = 0; i < 2; ++i)
        #pragma unroll
        for (int j = 0; j < 4; ++j)
            #pragma unroll
            for (int q = 0; q < 4; ++q) acc[i][j][q] = 0.f;

    fill(0, 0); fill(1, 1);

    for (int kt = 0; kt < KT_H; ++kt) {
        cp_wait<1>();
        __syncthreads();

        if (kt + 2 < KT_H) fill((kt + 2) % 3, kt + 2);
        else               cp_commit();

        const int s = kt % 3;
        const uint32_t Ab = sb + s * A_ST;
        const uint32_t Bb = sb + OFF_B + s * B_ST;
        #pragma unroll
        for (int kk = 0; kk < 2; ++kk) {
            uint32_t af[2][4];
            #pragma unroll
            for (int mt = 0; mt < 2; ++mt)
                ldsm_x4(af[mt], Ab + (wm * 32 + mt * 16 + (l & 15)) * 80
                                   + kk * 32 + (l >> 4) * 16);
            uint32_t bf[4][2];
            #pragma unroll
            for (int ntp = 0; ntp < 2; ++ntp) {
                const int krow = kk * 16 + ((l >> 3) & 1) * 8 + (l & 7);
                const int c    = wn * 4 + ntp * 2 + (l >> 4);
                uint32_t r[4];
                ldsm_x4_t(r, Bb + krow * 256 + ((c >> 3) * 128)
                             + (((c & 7) ^ (krow & 7)) << 4));
                bf[2 * ntp][0] = r[0];     bf[2 * ntp][1] = r[1];
                bf[2 * ntp + 1][0] = r[2]; bf[2 * ntp + 1][1] = r[3];
            }
            #pragma unroll
            for (int mt = 0; mt < 2; ++mt)
                #pragma unroll
                for (int nt = 0; nt < 4; ++nt)
                    mma_f16(acc[mt][nt], af[mt], bf[nt]);
        }
    }

    float* part = g_part[blockIdx.y];
    #pragma unroll
    for (int mt = 0; mt < 2; ++mt) {
        const int row = m0 + wm * 32 + mt * 16 + (l >> 2);
        #pragma unroll
        for (int nt = 0; nt < 4; ++nt) {
            const int col = wn * 32 + nt * 8 + (l & 3) * 2;
            *(float2*)&part[(size_t)row * DOUT + col] =
                make_float2(acc[mt][nt][0], acc[mt][nt][1]);
            *(float2*)&part[(size_t)(row + 8) * DOUT + col] =
                make_float2(acc[mt][nt][2], acc[mt][nt][3]);
        }
    }
}

__global__ void het_reduce(const float* __restrict__ ball, float* __restrict__ out) {
    const int i = blockIdx.x * blockDim.x + threadIdx.x;
    const int n4 = BATCH * DOUT / 4;
    if (i >= n4) return;
    float4 a = ((const float4*)g_part[0])[i];
    float4 b = ((const float4*)g_part[1])[i];
    const int col = (i * 4) & (DOUT - 1);
    float4 bv = *(const float4*)&ball[col];
    float x0 = a.x + b.x + bv.x; x0 = x0 > 0.f ? x0 : 0.01f * x0;
    float x1 = a.y + b.y + bv.y; x1 = x1 > 0.f ? x1 : 0.01f * x1;
    float x2 = a.z + b.z + bv.z; x2 = x2 > 0.f ? x2 : 0.01f * x2;
    float x3 = a.w + b.w + bv.w; x3 = x3 > 0.f ? x3 : 0.01f * x3;
    ((float4*)out)[i] = make_float4(x0, x1, x2, x3);
}

extern "C" void kernel_launch(void* const* d_in, const int* in_sizes, int n_in,
                              void* d_out, int out_size) {
    const float* features = (const float*)d_in[0];
    const float* W_edge   = (const float*)d_in[1];
    const float* b_edge   = (const float*)d_in[2];
    const float* W_het    = (const float*)d_in[3];
    const float* b_het    = (const float*)d_in[4];
    const int*   gid      = (const int*)d_in[5];
    float* out = (float*)d_out;

    __half* we; cudaGetSymbolAddress((void**)&we, g_WE);
    __half* wh; cudaGetSymbolAddress((void**)&wh, g_WH);

    const int n4e = NUM_EDGE * EDGE_IN * DOUT / 4;
    const int n4h = HET_IN * DOUT / 4;
    cvt_to_half<<<(n4e + 255) / 256, 256>>>((const float4*)W_edge, (__half2*)we, n4e);
    cvt_to_half<<<(n4h + 255) / 256, 256>>>((const float4*)W_het, (__half2*)wh, n4h);

    const int smem1 = 3 * (128 * 80) + 3 * (32 * 256);  // 55296
    const int smem2 = 3 * (64 * 80)  + 3 * (32 * 256);  // 39936

    cudaFuncSetAttribute(hetagg_edge,
                         cudaFuncAttributeMaxDynamicSharedMemorySize, smem1);
    cudaFuncSetAttribute(hetagg_het,
                         cudaFuncAttributeMaxDynamicSharedMemorySize, smem2);

    dim3 g1(BATCH / 128, NUM_EDGE);
    hetagg_edge<<<g1, 256, smem1>>>(features, gid, b_edge);

    dim3 g2(BATCH / 64, 2);
    hetagg_het<<<g2, 256, smem2>>>();

    const int n4o = BATCH * DOUT / 4;
    het_reduce<<<(n4o + 255) / 256, 256>>>(b_het, out);
}

// round 11
// speedup vs baseline: 1.3305x; 1.1715x over previous
#include <cuda_runtime.h>
#include <cuda_fp16.h>
#include <cstdint>

#define NUM_EDGE  14
#define NUM_NODES 10000
#define BATCH     8192
#define EDGE_IN   1536
#define HET_IN    1792
#define DOUT      128
#define SPLITK    4

__device__ __half g_agg[(size_t)BATCH * HET_IN];
__device__ __half g_WE [(size_t)NUM_EDGE * EDGE_IN * DOUT];
__device__ __half g_WH [(size_t)HET_IN * DOUT];
__device__ float  g_part[SPLITK][(size_t)BATCH * DOUT];

__device__ __forceinline__ uint32_t f2h2(float x, float y) {
    __half2 h = __floats2half2_rn(x, y);
    return *(uint32_t*)&h;
}

__device__ __forceinline__ void cp16(uint32_t s, const void* g) {
    asm volatile("cp.async.cg.shared.global [%0], [%1], 16;\n" :: "r"(s), "l"(g));
}
__device__ __forceinline__ void cp_commit() { asm volatile("cp.async.commit_group;\n"); }
template <int N> __device__ __forceinline__ void cp_wait() {
    asm volatile("cp.async.wait_group %0;\n" :: "n"(N));
}

__device__ __forceinline__ void ldsm_x4(uint32_t* r, uint32_t a) {
    asm volatile("ldmatrix.sync.aligned.m8n8.x4.shared.b16 {%0,%1,%2,%3}, [%4];"
        : "=r"(r[0]), "=r"(r[1]), "=r"(r[2]), "=r"(r[3]) : "r"(a));
}
__device__ __forceinline__ void ldsm_x4_t(uint32_t* r, uint32_t a) {
    asm volatile("ldmatrix.sync.aligned.m8n8.x4.trans.shared.b16 {%0,%1,%2,%3}, [%4];"
        : "=r"(r[0]), "=r"(r[1]), "=r"(r[2]), "=r"(r[3]) : "r"(a));
}
__device__ __forceinline__ void sts128(uint32_t a, uint32_t x, uint32_t y, uint32_t z, uint32_t w) {
    asm volatile("st.shared.v4.b32 [%0], {%1,%2,%3,%4};" :: "r"(a), "r"(x), "r"(y), "r"(z), "r"(w));
}

__device__ __forceinline__ void mma_f16(float* c, const uint32_t* a, const uint32_t* b) {
    asm volatile(
        "mma.sync.aligned.m16n8k16.row.col.f32.f16.f16.f32 "
        "{%0,%1,%2,%3}, {%4,%5,%6,%7}, {%8,%9}, {%0,%1,%2,%3};\n"
        : "+f"(c[0]), "+f"(c[1]), "+f"(c[2]), "+f"(c[3])
        : "r"(a[0]), "r"(a[1]), "r"(a[2]), "r"(a[3]), "r"(b[0]), "r"(b[1]));
}

// Single prep launch: converts BOTH weight tensors (keeps total launch count at 4
// so ncu's skip-5 capture lands on replay-2's hetagg_edge).
__global__ void cvt_all(const float4* __restrict__ we_src, __half2* __restrict__ we_dst,
                        const float4* __restrict__ wh_src, __half2* __restrict__ wh_dst,
                        int n4e, int n4h) {
    int i = blockIdx.x * blockDim.x + threadIdx.x;
    if (i < n4e) {
        float4 v = we_src[i];
        we_dst[2 * i]     = __floats2half2_rn(v.x, v.y);
        we_dst[2 * i + 1] = __floats2half2_rn(v.z, v.w);
    }
    int j = i - n4e;
    if (j >= 0 && j < n4h) {
        float4 v = wh_src[j];
        wh_dst[2 * j]     = __floats2half2_rn(v.x, v.y);
        wh_dst[2 * j + 1] = __floats2half2_rn(v.z, v.w);
    }
}

// ============================================================================
// GEMM1 (EDGE): R4 body VERBATIM -- BM=128, 256 thr, 8 warps (2x4 of 64x32),
// 3-slot ring, wait<1>, one K-tile per barrier. A gathered fp32->fp16 at STS.
// This exact configuration measured 178us; every variant tried was worse.
// ============================================================================
__global__ void __launch_bounds__(256, 2) hetagg_edge(
    const float* __restrict__ Afeat,
    const int*   __restrict__ gid,
    const float* __restrict__ ball)
{
    constexpr int KT    = EDGE_IN / 32;     // 48
    constexpr int A_ST  = 128 * 80;
    constexpr int B_ST  = 32 * 256;
    constexpr int OFF_B = 3 * A_ST;

    extern __shared__ char smem[];
    const uint32_t sb = (uint32_t)__cvta_generic_to_shared(smem);

    const int e    = blockIdx.y;
    const int tid  = threadIdx.x;
    const int l    = tid & 31;
    const int warp = tid >> 5;
    const int wm   = warp >> 2;
    const int wn   = warp & 3;
    const int m0   = blockIdx.x * 128;

    // ---- B loader: 2 cp16/thread/ktile
    const int bk = tid >> 3;
    const int bc = (tid & 7) * 2;
    const __half* bsrc = g_WE + (size_t)e * EDGE_IN * DOUT + (size_t)bk * DOUT + bc * 8;
    const uint32_t bdst0 = sb + OFF_B + bk * 256 + ((bc >> 3) * 128) + (((bc & 7) ^ (bk & 7)) * 16);
    const int bc1 = bc + 1;
    const uint32_t bdst1 = sb + OFF_B + bk * 256 + ((bc1 >> 3) * 128) + (((bc1 & 7) ^ (bk & 7)) * 16);
    auto cpB = [&](int s, int kt) {
        const __half* src = bsrc + (size_t)kt * 32 * DOUT;
        cp16(bdst0 + s * B_ST, src);
        cp16(bdst1 + s * B_ST, src + 8);
    };

    // ---- A loader: 2 threads/row, 16 floats/thread/ktile, convert at STS
    const int arow = tid >> 1, ah = tid & 1;
    const float* agF = Afeat + (size_t)e * NUM_NODES * EDGE_IN
                             + (size_t)gid[m0 + arow] * EDGE_IN + ah * 16;
    const uint32_t aSt = sb + arow * 80 + ah * 32;

    float4 av0, av1, av2, av3;
    auto ldA = [&](int kt) {
        const float4* p = (const float4*)(agF + kt * 32);
        av0 = p[0]; av1 = p[1]; av2 = p[2]; av3 = p[3];
    };
    auto stsA = [&](int s) {
        sts128(aSt + s * A_ST,
               f2h2(av0.x, av0.y), f2h2(av0.z, av0.w),
               f2h2(av1.x, av1.y), f2h2(av1.z, av1.w));
        sts128(aSt + s * A_ST + 16,
               f2h2(av2.x, av2.y), f2h2(av2.z, av2.w),
               f2h2(av3.x, av3.y), f2h2(av3.z, av3.w));
    };

    float acc[4][4][4];
    #pragma unroll
    for (int i = 0; i < 4; ++i)
        #pragma unroll
        for (int j = 0; j < 4; ++j)
            #pragma unroll
            for (int q = 0; q < 4; ++q) acc[i][j][q] = 0.f;

    // ---- prologue
    ldA(0); stsA(0); cpB(0, 0); cp_commit();
    ldA(1);          cpB(1, 1); cp_commit();

    int slot = 0, slotP = 1, slotF = 2;
    for (int kt = 0; kt < KT; ++kt) {
        cp_wait<1>();
        __syncthreads();

        if (kt + 1 < KT) stsA(slotP);
        if (kt + 2 < KT) { cpB(slotF, kt + 2); ldA(kt + 2); }
        cp_commit();

        const uint32_t Ab = sb + slot * A_ST;
        const uint32_t Bb = sb + OFF_B + slot * B_ST;
        #pragma unroll
        for (int kk = 0; kk < 2; ++kk) {
            uint32_t af[4][4];
            #pragma unroll
            for (int mt = 0; mt < 4; ++mt)
                ldsm_x4(af[mt], Ab + (wm * 64 + mt * 16 + (l & 15)) * 80
                                   + kk * 32 + (l >> 4) * 16);
            uint32_t bf[4][2];
            #pragma unroll
            for (int ntp = 0; ntp < 2; ++ntp) {
                const int krow = kk * 16 + ((l >> 3) & 1) * 8 + (l & 7);
                const int c    = wn * 4 + ntp * 2 + (l >> 4);
                uint32_t r[4];
                ldsm_x4_t(r, Bb + krow * 256 + ((c >> 3) * 128)
                             + (((c & 7) ^ (krow & 7)) << 4));
                bf[2 * ntp][0] = r[0];     bf[2 * ntp][1] = r[1];
                bf[2 * ntp + 1][0] = r[2]; bf[2 * ntp + 1][1] = r[3];
            }
            #pragma unroll
            for (int mt = 0; mt < 4; ++mt)
                #pragma unroll
                for (int nt = 0; nt < 4; ++nt)
                    mma_f16(acc[mt][nt], af[mt], bf[nt]);
        }

        const int t = slot; slot = slotP; slotP = slotF; slotF = t;
    }

    const float* bias = ball + e * DOUT;
    #pragma unroll
    for (int mt = 0; mt < 4; ++mt) {
        const int row = m0 + wm * 64 + mt * 16 + (l >> 2);
        #pragma unroll
        for (int nt = 0; nt < 4; ++nt) {
            const int col = wn * 32 + nt * 8 + (l & 3) * 2;
            const float2 bv = *(const float2*)&bias[col];
            float x0 = acc[mt][nt][0] + bv.x; x0 = x0 > 0.f ? x0 : 0.01f * x0;
            float x1 = acc[mt][nt][1] + bv.y; x1 = x1 > 0.f ? x1 : 0.01f * x1;
            float x2 = acc[mt][nt][2] + bv.x; x2 = x2 > 0.f ? x2 : 0.01f * x2;
            float x3 = acc[mt][nt][3] + bv.y; x3 = x3 > 0.f ? x3 : 0.01f * x3;
            *(__half2*)&g_agg[(size_t)row * HET_IN + e * DOUT + col]       = __floats2half2_rn(x0, x1);
            *(__half2*)&g_agg[(size_t)(row + 8) * HET_IN + e * DOUT + col] = __floats2half2_rn(x2, x3);
        }
    }
}

// ============================================================================
// GEMM2 (HET): split-K=4 (proven R8 code, constant change). BM=64, 8 warps,
// 3-slot ring. Partials -> g_part[split]. grid (128, 4).
// ============================================================================
__global__ void __launch_bounds__(256, 3) hetagg_het(void)
{
    constexpr int KSEG  = HET_IN / SPLITK;     // 448
    constexpr int KT_H  = KSEG / 32;           // 14
    constexpr int A_ST  = 64 * 80;
    constexpr int B_ST  = 32 * 256;
    constexpr int OFF_B = 3 * A_ST;

    extern __shared__ char smem[];
    const uint32_t sb = (uint32_t)__cvta_generic_to_shared(smem);

    const int tid  = threadIdx.x;
    const int l    = tid & 31;
    const int warp = tid >> 5;
    const int wm   = warp >> 2;
    const int wn   = warp & 3;
    const int m0   = blockIdx.x * 64;
    const int kOff = blockIdx.y * KSEG;

    const int bk = tid >> 3;
    const int bc = (tid & 7) * 2;
    const __half* bsrc = g_WH + (size_t)(kOff + bk) * DOUT + bc * 8;
    const uint32_t bdst0 = sb + OFF_B + bk * 256 + ((bc >> 3) * 128) + (((bc & 7) ^ (bk & 7)) * 16);
    const int bc1 = bc + 1;
    const uint32_t bdst1 = sb + OFF_B + bk * 256 + ((bc1 >> 3) * 128) + (((bc1 & 7) ^ (bk & 7)) * 16);

    const int arow = tid >> 2, ac = tid & 3;
    const __half* agH  = g_agg + (size_t)(m0 + arow) * HET_IN + kOff + ac * 8;
    const uint32_t adst = sb + arow * 80 + ac * 16;

    auto fill = [&](int s, int kt) {
        cp16(adst + s * A_ST, agH + kt * 32);
        const __half* src = bsrc + (size_t)kt * 32 * DOUT;
        cp16(bdst0 + s * B_ST, src);
        cp16(bdst1 + s * B_ST, src + 8);
        cp_commit();
    };

    float acc[2][4][4];
    #pragma unroll
    for (int i = 0; i < 2; ++i)
        #pragma unroll
        for (int j = 0; j < 4; ++j)
            #pragma unroll
            for (int q = 0; q < 4; ++q) acc[i][j][q] = 0.f;

    fill(0, 0); fill(1, 1);

    for (int kt = 0; kt < KT_H; ++kt) {
        cp_wait<1>();
        __syncthreads();

        if (kt + 2 < KT_H) fill((kt + 2) % 3, kt + 2);
        else               cp_commit();

        const int s = kt % 3;
        const uint32_t Ab = sb + s * A_ST;
        const uint32_t Bb = sb + OFF_B + s * B_ST;
        #pragma unroll
        for (int kk = 0; kk < 2; ++kk) {
            uint32_t af[2][4];
            #pragma unroll
            for (int mt = 0; mt < 2; ++mt)
                ldsm_x4(af[mt], Ab + (wm * 32 + mt * 16 + (l & 15)) * 80
                                   + kk * 32 + (l >> 4) * 16);
            uint32_t bf[4][2];
            #pragma unroll
            for (int ntp = 0; ntp < 2; ++ntp) {
                const int krow = kk * 16 + ((l >> 3) & 1) * 8 + (l & 7);
                const int c    = wn * 4 + ntp * 2 + (l >> 4);
                uint32_t r[4];
                ldsm_x4_t(r, Bb + krow * 256 + ((c >> 3) * 128)
                             + (((c & 7) ^ (krow & 7)) << 4));
                bf[2 * ntp][0] = r[0];     bf[2 * ntp][1] = r[1];
                bf[2 * ntp + 1][0] = r[2]; bf[2 * ntp + 1][1] = r[3];
            }
            #pragma unroll
            for (int mt = 0; mt < 2; ++mt)
                #pragma unroll
                for (int nt = 0; nt < 4; ++nt)
                    mma_f16(acc[mt][nt], af[mt], bf[nt]);
        }
    }

    float* part = g_part[blockIdx.y];
    #pragma unroll
    for (int mt = 0; mt < 2; ++mt) {
        const int row = m0 + wm * 32 + mt * 16 + (l >> 2);
        #pragma unroll
        for (int nt = 0; nt < 4; ++nt) {
            const int col = wn * 32 + nt * 8 + (l & 3) * 2;
            *(float2*)&part[(size_t)row * DOUT + col] =
                make_float2(acc[mt][nt][0], acc[mt][nt][1]);
            *(float2*)&part[(size_t)(row + 8) * DOUT + col] =
                make_float2(acc[mt][nt][2], acc[mt][nt][3]);
        }
    }
}

__global__ void het_reduce(const float* __restrict__ ball, float* __restrict__ out) {
    const int i = blockIdx.x * blockDim.x + threadIdx.x;
    const int n4 = BATCH * DOUT / 4;
    if (i >= n4) return;
    float4 a = ((const float4*)g_part[0])[i];
    float4 b = ((const float4*)g_part[1])[i];
    float4 c = ((const float4*)g_part[2])[i];
    float4 d = ((const float4*)g_part[3])[i];
    const int col = (i * 4) & (DOUT - 1);
    float4 bv = *(const float4*)&ball[col];
    float x0 = a.x + b.x + c.x + d.x + bv.x; x0 = x0 > 0.f ? x0 : 0.01f * x0;
    float x1 = a.y + b.y + c.y + d.y + bv.y; x1 = x1 > 0.f ? x1 : 0.01f * x1;
    float x2 = a.z + b.z + c.z + d.z + bv.z; x2 = x2 > 0.f ? x2 : 0.01f * x2;
    float x3 = a.w + b.w + c.w + d.w + bv.w; x3 = x3 > 0.f ? x3 : 0.01f * x3;
    ((float4*)out)[i] = make_float4(x0, x1, x2, x3);
}

extern "C" void kernel_launch(void* const* d_in, const int* in_sizes, int n_in,
                              void* d_out, int out_size) {
    const float* features = (const float*)d_in[0];
    const float* W_edge   = (const float*)d_in[1];
    const float* b_edge   = (const float*)d_in[2];
    const float* W_het    = (const float*)d_in[3];
    const float* b_het    = (const float*)d_in[4];
    const int*   gid      = (const int*)d_in[5];
    float* out = (float*)d_out;

    __half* we; cudaGetSymbolAddress((void**)&we, g_WE);
    __half* wh; cudaGetSymbolAddress((void**)&wh, g_WH);

    const int n4e = NUM_EDGE * EDGE_IN * DOUT / 4;
    const int n4h = HET_IN * DOUT / 4;
    cvt_all<<<(n4e + n4h + 255) / 256, 256>>>(
        (const float4*)W_edge, (__half2*)we,
        (const float4*)W_het,  (__half2*)wh, n4e, n4h);

    const int smem1 = 3 * (128 * 80) + 3 * (32 * 256);  // 55296
    const int smem2 = 3 * (64 * 80)  + 3 * (32 * 256);  // 39936

    cudaFuncSetAttribute(hetagg_edge,
                         cudaFuncAttributeMaxDynamicSharedMemorySize, smem1);
    cudaFuncSetAttribute(hetagg_het,
                         cudaFuncAttributeMaxDynamicSharedMemorySize, smem2);

    dim3 g1(BATCH / 128, NUM_EDGE);
    hetagg_edge<<<g1, 256, smem1>>>(features, gid, b_edge);

    dim3 g2(BATCH / 64, SPLITK);
    hetagg_het<<<g2, 256, smem2>>>();

    const int n4o = BATCH * DOUT / 4;
    het_reduce<<<(n4o + 255) / 256, 256>>>(b_het, out);
}